// round 1
// baseline (speedup 1.0000x reference)
#include <cuda_runtime.h>

#define CCH 16
#define GSZ 300

// Channel-innermost scratch copies (allocation-free: __device__ globals).
// Pt[i][y][x][c], Lt[i][g][c]
__device__ float g_planes_t[3 * GSZ * GSZ * CCH];   // 17.28 MB
__device__ float g_lines_t[3 * GSZ * CCH];          // 57.6 KB

// ---------------------------------------------------------------------------
// Transpose planes (3,C,G,G) -> (3,G,G,C). Reads coalesced (consecutive x per
// warp per channel), writes 64B contiguous per thread as 4x float4.
// ---------------------------------------------------------------------------
__global__ void transpose_planes_kernel(const float* __restrict__ planes) {
    int idx = blockIdx.x * blockDim.x + threadIdx.x;     // over 3*G*G texels
    if (idx >= 3 * GSZ * GSZ) return;
    int x  = idx % GSZ;
    int yi = idx / GSZ;
    int y  = yi % GSZ;
    int i  = yi / GSZ;

    const float* src = planes + ((size_t)i * CCH) * GSZ * GSZ + (size_t)y * GSZ + x;
    float buf[CCH];
#pragma unroll
    for (int c = 0; c < CCH; c++)
        buf[c] = __ldg(src + (size_t)c * GSZ * GSZ);

    float4* dst = reinterpret_cast<float4*>(g_planes_t + (size_t)idx * CCH);
#pragma unroll
    for (int c4 = 0; c4 < CCH / 4; c4++)
        dst[c4] = make_float4(buf[4 * c4 + 0], buf[4 * c4 + 1],
                              buf[4 * c4 + 2], buf[4 * c4 + 3]);
}

// Transpose lines (3,C,G) -> (3,G,C)
__global__ void transpose_lines_kernel(const float* __restrict__ lines) {
    int idx = blockIdx.x * blockDim.x + threadIdx.x;     // over 3*G
    if (idx >= 3 * GSZ) return;
    int g = idx % GSZ;
    int i = idx / GSZ;

    float buf[CCH];
#pragma unroll
    for (int c = 0; c < CCH; c++)
        buf[c] = __ldg(lines + ((size_t)i * CCH + c) * GSZ + g);

    float4* dst = reinterpret_cast<float4*>(g_lines_t + (size_t)idx * CCH);
#pragma unroll
    for (int c4 = 0; c4 < CCH / 4; c4++)
        dst[c4] = make_float4(buf[4 * c4 + 0], buf[4 * c4 + 1],
                              buf[4 * c4 + 2], buf[4 * c4 + 3]);
}

// ---------------------------------------------------------------------------
// Main sampler: one thread per point, all 3 modes, 48 outputs.
// ---------------------------------------------------------------------------
__device__ __forceinline__ void lerp_idx(float coord, int size,
                                         int& i0, int& i1, float& w) {
    float x  = (coord + 1.0f) * 0.5f * (float)(size - 1);
    float xf = floorf(x);
    xf = fminf(fmaxf(xf, 0.0f), (float)(size - 1));
    i0 = (int)xf;
    i1 = min(i0 + 1, size - 1);
    w  = x - xf;
}

__global__ void vm_sample_kernel(const float* __restrict__ xyz,
                                 float* __restrict__ out, int N) {
    int n = blockIdx.x * blockDim.x + threadIdx.x;
    if (n >= N) return;

    float c0 = __ldg(xyz + 3 * n + 0);
    float c1 = __ldg(xyz + 3 * n + 1);
    float c2 = __ldg(xyz + 3 * n + 2);
    float coords[3] = {c0, c1, c2};

    // matMode = ((1,2),(0,2),(0,1)) : gx = coords[a], gy = coords[b]
    const int ma[3] = {1, 0, 0};
    const int mb[3] = {2, 2, 1};

#pragma unroll
    for (int i = 0; i < 3; i++) {
        float gx = coords[ma[i]];
        float gy = coords[mb[i]];
        float gl = coords[i];

        int x0, x1, y0, y1, z0, z1;
        float wx, wy, wz;
        lerp_idx(gx, GSZ, x0, x1, wx);
        lerp_idx(gy, GSZ, y0, y1, wy);
        lerp_idx(gl, GSZ, z0, z1, wz);

        float w00 = (1.0f - wx) * (1.0f - wy);
        float w01 = wx * (1.0f - wy);
        float w10 = (1.0f - wx) * wy;
        float w11 = wx * wy;

        const float4* p00 = reinterpret_cast<const float4*>(
            g_planes_t + (((size_t)i * GSZ + y0) * GSZ + x0) * CCH);
        const float4* p01 = reinterpret_cast<const float4*>(
            g_planes_t + (((size_t)i * GSZ + y0) * GSZ + x1) * CCH);
        const float4* p10 = reinterpret_cast<const float4*>(
            g_planes_t + (((size_t)i * GSZ + y1) * GSZ + x0) * CCH);
        const float4* p11 = reinterpret_cast<const float4*>(
            g_planes_t + (((size_t)i * GSZ + y1) * GSZ + x1) * CCH);
        const float4* l0 = reinterpret_cast<const float4*>(
            g_lines_t + ((size_t)i * GSZ + z0) * CCH);
        const float4* l1 = reinterpret_cast<const float4*>(
            g_lines_t + ((size_t)i * GSZ + z1) * CCH);

        float one_wz = 1.0f - wz;

#pragma unroll
        for (int c4 = 0; c4 < CCH / 4; c4++) {
            float4 a = p00[c4];
            float4 b = p01[c4];
            float4 c = p10[c4];
            float4 d = p11[c4];

            float4 acc;
            acc.x = w00 * a.x + w01 * b.x + w10 * c.x + w11 * d.x;
            acc.y = w00 * a.y + w01 * b.y + w10 * c.y + w11 * d.y;
            acc.z = w00 * a.z + w01 * b.z + w10 * c.z + w11 * d.z;
            acc.w = w00 * a.w + w01 * b.w + w10 * c.w + w11 * d.w;

            float4 e = l0[c4];
            float4 f = l1[c4];
            float4 lv;
            lv.x = e.x * one_wz + f.x * wz;
            lv.y = e.y * one_wz + f.y * wz;
            lv.z = e.z * one_wz + f.z * wz;
            lv.w = e.w * one_wz + f.w * wz;

            int cbase = i * CCH + 4 * c4;
            out[(size_t)(cbase + 0) * N + n] = acc.x * lv.x;
            out[(size_t)(cbase + 1) * N + n] = acc.y * lv.y;
            out[(size_t)(cbase + 2) * N + n] = acc.z * lv.z;
            out[(size_t)(cbase + 3) * N + n] = acc.w * lv.w;
        }
    }
}

extern "C" void kernel_launch(void* const* d_in, const int* in_sizes, int n_in,
                              void* d_out, int out_size) {
    const float* xyz    = (const float*)d_in[0];
    const float* planes = (const float*)d_in[1];
    const float* lines  = (const float*)d_in[2];
    float* out = (float*)d_out;

    int N = in_sizes[0] / 3;

    {
        int total = 3 * GSZ * GSZ;
        int threads = 256;
        transpose_planes_kernel<<<(total + threads - 1) / threads, threads>>>(planes);
    }
    {
        int total = 3 * GSZ;
        int threads = 256;
        transpose_lines_kernel<<<(total + threads - 1) / threads, threads>>>(lines);
    }
    {
        int threads = 256;
        vm_sample_kernel<<<(N + threads - 1) / threads, threads>>>(xyz, out, N);
    }
}

// round 2
// speedup vs baseline: 2.4564x; 2.4564x over previous
#include <cuda_runtime.h>

#define CCH 16
#define GSZ 300

// Channel-innermost scratch copies (allocation-free: __device__ globals).
// Pt[i][y][x][c], Lt[i][g][c]
__device__ float g_planes_t[3 * GSZ * GSZ * CCH];   // 17.28 MB
__device__ float g_lines_t[3 * GSZ * CCH];          // 57.6 KB

// ---------------------------------------------------------------------------
// Transpose planes (3,C,G,G) -> (3,G,G,C).
// ---------------------------------------------------------------------------
__global__ void transpose_planes_kernel(const float* __restrict__ planes) {
    int idx = blockIdx.x * blockDim.x + threadIdx.x;     // over 3*G*G texels
    if (idx >= 3 * GSZ * GSZ) return;
    int x  = idx % GSZ;
    int yi = idx / GSZ;
    int y  = yi % GSZ;
    int i  = yi / GSZ;

    const float* src = planes + ((size_t)i * CCH) * GSZ * GSZ + (size_t)y * GSZ + x;
    float buf[CCH];
#pragma unroll
    for (int c = 0; c < CCH; c++)
        buf[c] = __ldg(src + (size_t)c * GSZ * GSZ);

    float4* dst = reinterpret_cast<float4*>(g_planes_t + (size_t)idx * CCH);
#pragma unroll
    for (int c4 = 0; c4 < CCH / 4; c4++)
        dst[c4] = make_float4(buf[4 * c4 + 0], buf[4 * c4 + 1],
                              buf[4 * c4 + 2], buf[4 * c4 + 3]);
}

// Transpose lines (3,C,G) -> (3,G,C)
__global__ void transpose_lines_kernel(const float* __restrict__ lines) {
    int idx = blockIdx.x * blockDim.x + threadIdx.x;     // over 3*G
    if (idx >= 3 * GSZ) return;
    int g = idx % GSZ;
    int i = idx / GSZ;

    float buf[CCH];
#pragma unroll
    for (int c = 0; c < CCH; c++)
        buf[c] = __ldg(lines + ((size_t)i * CCH + c) * GSZ + g);

    float4* dst = reinterpret_cast<float4*>(g_lines_t + (size_t)idx * CCH);
#pragma unroll
    for (int c4 = 0; c4 < CCH / 4; c4++)
        dst[c4] = make_float4(buf[4 * c4 + 0], buf[4 * c4 + 1],
                              buf[4 * c4 + 2], buf[4 * c4 + 3]);
}

// ---------------------------------------------------------------------------
// Main sampler: 4 lanes per point (one float4 of channels each).
// A warp covers 8 points; every gather LDG.128 touches only 8 distinct 64B
// texels -> ~8 L1tex wavefronts/instr instead of 32.
// ---------------------------------------------------------------------------
__device__ __forceinline__ void lerp_idx(float coord, int size,
                                         int& i0, int& i1, float& w) {
    float x  = (coord + 1.0f) * 0.5f * (float)(size - 1);
    float xf = floorf(x);
    xf = fminf(fmaxf(xf, 0.0f), (float)(size - 1));
    i0 = (int)xf;
    i1 = min(i0 + 1, size - 1);
    w  = x - xf;
}

__global__ void vm_sample_kernel(const float* __restrict__ xyz,
                                 float* __restrict__ out, int N) {
    int warpGlobal = (blockIdx.x * blockDim.x + threadIdx.x) >> 5;
    int lane = threadIdx.x & 31;
    int q = lane >> 2;          // point within warp (0..7)
    int r = lane & 3;           // channel quad (0..3)
    int base = warpGlobal * 8;  // first point of this warp
    if (base >= N) return;

    // Coalesced coord fetch: first 24 lanes read xyz[base*3 .. base*3+23]
    float v = 0.0f;
    {
        long long gidx = (long long)base * 3 + lane;
        if (lane < 24 && gidx < (long long)N * 3)
            v = __ldg(xyz + gidx);
    }
    float c0 = __shfl_sync(0xffffffffu, v, q * 3 + 0);
    float c1 = __shfl_sync(0xffffffffu, v, q * 3 + 1);
    float c2 = __shfl_sync(0xffffffffu, v, q * 3 + 2);

    int n = base + q;
    if (n >= N) return;

    float coords[3] = {c0, c1, c2};
    // matMode = ((1,2),(0,2),(0,1)) : gx = coords[a], gy = coords[b]
    const int ma[3] = {1, 0, 0};
    const int mb[3] = {2, 2, 1};

#pragma unroll
    for (int i = 0; i < 3; i++) {
        float gx = coords[ma[i]];
        float gy = coords[mb[i]];
        float gl = coords[i];

        int x0, x1, y0, y1, z0, z1;
        float wx, wy, wz;
        lerp_idx(gx, GSZ, x0, x1, wx);
        lerp_idx(gy, GSZ, y0, y1, wy);
        lerp_idx(gl, GSZ, z0, z1, wz);

        float w00 = (1.0f - wx) * (1.0f - wy);
        float w01 = wx * (1.0f - wy);
        float w10 = (1.0f - wx) * wy;
        float w11 = wx * wy;
        float one_wz = 1.0f - wz;

        size_t pb = ((size_t)i * GSZ) * GSZ;
        const float4* p00 = reinterpret_cast<const float4*>(
            g_planes_t + ((pb + (size_t)y0 * GSZ + x0) * CCH + r * 4));
        const float4* p01 = reinterpret_cast<const float4*>(
            g_planes_t + ((pb + (size_t)y0 * GSZ + x1) * CCH + r * 4));
        const float4* p10 = reinterpret_cast<const float4*>(
            g_planes_t + ((pb + (size_t)y1 * GSZ + x0) * CCH + r * 4));
        const float4* p11 = reinterpret_cast<const float4*>(
            g_planes_t + ((pb + (size_t)y1 * GSZ + x1) * CCH + r * 4));
        const float4* l0 = reinterpret_cast<const float4*>(
            g_lines_t + (((size_t)i * GSZ + z0) * CCH + r * 4));
        const float4* l1 = reinterpret_cast<const float4*>(
            g_lines_t + (((size_t)i * GSZ + z1) * CCH + r * 4));

        float4 a = *p00;
        float4 b = *p01;
        float4 c = *p10;
        float4 d = *p11;

        float4 acc;
        acc.x = w00 * a.x + w01 * b.x + w10 * c.x + w11 * d.x;
        acc.y = w00 * a.y + w01 * b.y + w10 * c.y + w11 * d.y;
        acc.z = w00 * a.z + w01 * b.z + w10 * c.z + w11 * d.z;
        acc.w = w00 * a.w + w01 * b.w + w10 * c.w + w11 * d.w;

        float4 e = *l0;
        float4 f = *l1;
        float4 lv;
        lv.x = e.x * one_wz + f.x * wz;
        lv.y = e.y * one_wz + f.y * wz;
        lv.z = e.z * one_wz + f.z * wz;
        lv.w = e.w * one_wz + f.w * wz;

        int cbase = i * CCH + 4 * r;
        out[(size_t)(cbase + 0) * N + n] = acc.x * lv.x;
        out[(size_t)(cbase + 1) * N + n] = acc.y * lv.y;
        out[(size_t)(cbase + 2) * N + n] = acc.z * lv.z;
        out[(size_t)(cbase + 3) * N + n] = acc.w * lv.w;
    }
}

extern "C" void kernel_launch(void* const* d_in, const int* in_sizes, int n_in,
                              void* d_out, int out_size) {
    const float* xyz    = (const float*)d_in[0];
    const float* planes = (const float*)d_in[1];
    const float* lines  = (const float*)d_in[2];
    float* out = (float*)d_out;

    int N = in_sizes[0] / 3;

    {
        int total = 3 * GSZ * GSZ;
        int threads = 256;
        transpose_planes_kernel<<<(total + threads - 1) / threads, threads>>>(planes);
    }
    {
        int total = 3 * GSZ;
        int threads = 256;
        transpose_lines_kernel<<<(total + threads - 1) / threads, threads>>>(lines);
    }
    {
        // 4 threads per point, 8 points per warp
        long long totalThreads = (long long)((N + 7) / 8) * 32;
        int threads = 256;
        long long blocks = (totalThreads + threads - 1) / threads;
        vm_sample_kernel<<<(int)blocks, threads>>>(xyz, out, N);
    }
}